// round 1
// baseline (speedup 1.0000x reference)
#include <cuda_runtime.h>
#include <cstdint>
#include <cstddef>

// Problem constants
#define NB  128
#define NR  500
#define NN  500
#define NK  10
#define NE  128
#define NH1 640
#define NKE 1280            // NK*NE
#define NM  (NB * NR)       // 64000 rows

// Scratch (static device arrays; no runtime allocation allowed)
__device__ float g_emb[(size_t)NM * NKE];  // 327.7 MB
__device__ float g_h[(size_t)NM * NH1];    // 163.8 MB

__device__ __forceinline__ uint32_t f2tf(float x) {
    uint32_t u;
    asm("cvt.rna.tf32.f32 %0, %1;" : "=r"(u) : "f"(x));
    return u;
}

// ---------------------------------------------------------------------------
// Kernel 1: top-K nearest unvisited + gather + pad-avg -> g_emb (row, k*E+e)
// One warp per (b, r) row. 4 warps / block.
// ---------------------------------------------------------------------------
__global__ void __launch_bounds__(128) prep_kernel(
    const int*   __restrict__ current,
    const float* __restrict__ distance,
    const float* __restrict__ masked,
    const float* __restrict__ enc)
{
    const int row  = blockIdx.x * 4 + (threadIdx.x >> 5);
    const int lane = threadIdx.x & 31;
    const int b    = row / NR;
    const float FINF = __int_as_float(0x7f800000);

    const float* mrow = masked + (size_t)row * NN;
    const int    cur  = current[row];
    const float* drow = distance + ((size_t)b * NN + cur) * NN;

    // Each lane owns candidates n = lane + 32*j, j in [0,16)
    float v[16];
#pragma unroll
    for (int j = 0; j < 16; j++) {
        int n = lane + 32 * j;
        float val = FINF;
        if (n < NN) {
            float m = __ldg(mrow + n);        // 0.0 (unvisited) or -inf (visited)
            if (m > -1e37f) val = __ldg(drow + n);
        }
        v[j] = val;
    }

    // 10 rounds of warp-wide argmin with stable (smallest-index) tie-break.
    int sel[NK];
#pragma unroll
    for (int k = 0; k < NK; k++) {
        float bv = v[0]; int bj = 0;
#pragma unroll
        for (int j = 1; j < 16; j++)
            if (v[j] < bv) { bv = v[j]; bj = j; }  // within-lane: lower j == lower n
        int bn = lane + 32 * bj;
#pragma unroll
        for (int off = 16; off > 0; off >>= 1) {
            float ov = __shfl_xor_sync(0xffffffffu, bv, off);
            int   on = __shfl_xor_sync(0xffffffffu, bn, off);
            if (ov < bv || (ov == bv && on < bn)) { bv = ov; bn = on; }
        }
        if (bv < FINF) {
            sel[k] = bn;
            // clear the winner without dynamic indexing (keep v[] in registers)
            bool mine = (bn & 31) == lane;
            int  cj   = bn >> 5;
#pragma unroll
            for (int j = 0; j < 16; j++)
                if (mine && cj == j) v[j] = FINF;
        } else {
            sel[k] = NN;  // padding index
        }
    }

    // Gather + pad-avg. Each lane handles 4 contiguous channels (float4).
    float4 acc = make_float4(0.f, 0.f, 0.f, 0.f);
    int cnt = 0;
#pragma unroll
    for (int k = 0; k < NK; k++) {
        if (sel[k] < NN) {
            cnt++;
            float4 e = *(const float4*)(enc + ((size_t)b * NN + sel[k]) * NE + lane * 4);
            acc.x += e.x; acc.y += e.y; acc.z += e.z; acc.w += e.w;
        }
    }
    float cf = (cnt > 0) ? (float)cnt : 1.0f;   // cnt==0 -> acc==0 -> mean 0
    float4 mean = make_float4(acc.x / cf, acc.y / cf, acc.z / cf, acc.w / cf);

    float* erow = g_emb + (size_t)row * NKE + lane * 4;
#pragma unroll
    for (int k = 0; k < NK; k++) {
        float4 o;
        if (sel[k] < NN)
            o = *(const float4*)(enc + ((size_t)b * NN + sel[k]) * NE + lane * 4);
        else
            o = mean;
        *(float4*)(erow + k * NE) = o;
    }
}

// ---------------------------------------------------------------------------
// tf32 mma.sync GEMM:  C[M,Nn] = A[M,Kk] * W[Nn,Kk]^T  (+bias, optional ReLU)
// Block tile 128x64, BK=32, 8 warps, warp tile 32x32 (2x4 m16n8k8 MMAs).
// WHICH==1: g_emb -> g_h (w1, b1, ReLU).  WHICH==2: g_h -> out (w2, b2).
// ---------------------------------------------------------------------------
template<int WHICH>
__global__ void __launch_bounds__(256) gemm_kernel(
    const float* __restrict__ W,
    const float* __restrict__ bias,
    float*       __restrict__ Cout)
{
    constexpr int  Kk   = (WHICH == 1) ? NKE : NH1;
    constexpr int  Nn   = (WHICH == 1) ? NH1 : NE;
    constexpr bool RELU = (WHICH == 1);
    const float* A = (WHICH == 1) ? g_emb : g_h;
    float*       C = (WHICH == 1) ? g_h   : Cout;

    constexpr int BM = 128, BN = 64, BK = 32;
    __shared__ uint32_t As[BM][BK + 4];   // padded: conflict-free frag reads
    __shared__ uint32_t Bs[BN][BK + 4];

    const int m0   = blockIdx.y * BM;
    const int n0   = blockIdx.x * BN;
    const int t    = threadIdx.x;
    const int lane = t & 31;
    const int w    = t >> 5;
    const int wm   = w >> 1;   // 0..3  (M direction)
    const int wn   = w & 1;    // 0..1  (N direction)

    float acc[2][4][4];
#pragma unroll
    for (int i = 0; i < 2; i++)
#pragma unroll
        for (int j = 0; j < 4; j++)
#pragma unroll
            for (int q = 0; q < 4; q++) acc[i][j][q] = 0.f;

    const int tr = t >> 3;         // 0..31
    const int tc = (t & 7) * 4;    // 0..28

    for (int k0 = 0; k0 < Kk; k0 += BK) {
        // Stage A tile (128 x 32), converting fp32 -> tf32 (rna)
#pragma unroll
        for (int p = 0; p < 4; p++) {
            int gr = tr + p * 32;
            float4 x = *(const float4*)(A + (size_t)(m0 + gr) * Kk + k0 + tc);
            As[gr][tc + 0] = f2tf(x.x);
            As[gr][tc + 1] = f2tf(x.y);
            As[gr][tc + 2] = f2tf(x.z);
            As[gr][tc + 3] = f2tf(x.w);
        }
        // Stage W tile (64 x 32)
#pragma unroll
        for (int p = 0; p < 2; p++) {
            int gr = tr + p * 32;
            float4 x = *(const float4*)(W + (size_t)(n0 + gr) * Kk + k0 + tc);
            Bs[gr][tc + 0] = f2tf(x.x);
            Bs[gr][tc + 1] = f2tf(x.y);
            Bs[gr][tc + 2] = f2tf(x.z);
            Bs[gr][tc + 3] = f2tf(x.w);
        }
        __syncthreads();

#pragma unroll
        for (int kk = 0; kk < BK; kk += 8) {
            uint32_t a[2][4];
#pragma unroll
            for (int mt = 0; mt < 2; mt++) {
                int mr = wm * 32 + mt * 16 + (lane >> 2);
                int kc = kk + (lane & 3);
                a[mt][0] = As[mr][kc];
                a[mt][1] = As[mr + 8][kc];
                a[mt][2] = As[mr][kc + 4];
                a[mt][3] = As[mr + 8][kc + 4];
            }
            uint32_t bb[4][2];
#pragma unroll
            for (int nt = 0; nt < 4; nt++) {
                int nc = wn * 32 + nt * 8 + (lane >> 2);
                int kc = kk + (lane & 3);
                bb[nt][0] = Bs[nc][kc];
                bb[nt][1] = Bs[nc][kc + 4];
            }
#pragma unroll
            for (int mt = 0; mt < 2; mt++)
#pragma unroll
                for (int nt = 0; nt < 4; nt++) {
                    asm volatile(
                        "mma.sync.aligned.m16n8k8.row.col.f32.tf32.tf32.f32 "
                        "{%0,%1,%2,%3}, {%4,%5,%6,%7}, {%8,%9}, {%0,%1,%2,%3};\n"
                        : "+f"(acc[mt][nt][0]), "+f"(acc[mt][nt][1]),
                          "+f"(acc[mt][nt][2]), "+f"(acc[mt][nt][3])
                        : "r"(a[mt][0]), "r"(a[mt][1]), "r"(a[mt][2]), "r"(a[mt][3]),
                          "r"(bb[nt][0]), "r"(bb[nt][1]));
                }
        }
        __syncthreads();
    }

    // Epilogue: bias (+ReLU), float2 stores
#pragma unroll
    for (int mt = 0; mt < 2; mt++) {
#pragma unroll
        for (int nt = 0; nt < 4; nt++) {
            int mr = m0 + wm * 32 + mt * 16 + (lane >> 2);
            int nc = n0 + wn * 32 + nt * 8 + (lane & 3) * 2;
            float bx = __ldg(bias + nc);
            float by = __ldg(bias + nc + 1);
            float2 r0 = make_float2(acc[mt][nt][0] + bx, acc[mt][nt][1] + by);
            float2 r1 = make_float2(acc[mt][nt][2] + bx, acc[mt][nt][3] + by);
            if (RELU) {
                r0.x = fmaxf(r0.x, 0.f); r0.y = fmaxf(r0.y, 0.f);
                r1.x = fmaxf(r1.x, 0.f); r1.y = fmaxf(r1.y, 0.f);
            }
            *(float2*)(C + (size_t)mr * Nn + nc)       = r0;
            *(float2*)(C + (size_t)(mr + 8) * Nn + nc) = r1;
        }
    }
}

// ---------------------------------------------------------------------------
extern "C" void kernel_launch(void* const* d_in, const int* in_sizes, int n_in,
                              void* d_out, int out_size)
{
    const int*   current  = (const int*)  d_in[0];
    const float* distance = (const float*)d_in[1];
    const float* masked   = (const float*)d_in[2];
    const float* enc      = (const float*)d_in[3];
    const float* w1       = (const float*)d_in[4];
    const float* b1       = (const float*)d_in[5];
    const float* w2       = (const float*)d_in[6];
    const float* b2       = (const float*)d_in[7];
    float* out = (float*)d_out;

    prep_kernel<<<NM / 4, 128>>>(current, distance, masked, enc);
    gemm_kernel<1><<<dim3(NH1 / 64, NM / 128), 256>>>(w1, b1, nullptr);
    gemm_kernel<2><<<dim3(NE  / 64, NM / 128), 256>>>(w2, b2, out);
}

// round 2
// speedup vs baseline: 1.2737x; 1.2737x over previous
#include <cuda_runtime.h>
#include <cstdint>
#include <cstddef>

// Problem constants
#define NB  128
#define NR  500
#define NN  500
#define NK  10
#define NE  128
#define NH1 640
#define NKE 1280            // NK*NE
#define NM  (NB * NR)       // 64000 rows

// Scratch (static device arrays; no runtime allocation allowed)
__device__ float g_emb[(size_t)NM * NKE];  // 327.7 MB, tf32-rounded
__device__ float g_h[(size_t)NM * NH1];    // 163.8 MB, tf32-rounded
__device__ float g_w1[NH1 * NKE];          // tf32-rounded w1
__device__ float g_w2[NE * NH1];           // tf32-rounded w2

__device__ __forceinline__ float f2tf_f(float x) {
    uint32_t u;
    asm("cvt.rna.tf32.f32 %0, %1;" : "=r"(u) : "f"(x));
    return __uint_as_float(u);
}

// ---------------------------------------------------------------------------
// Kernel 0: round weights to tf32 once per launch
// ---------------------------------------------------------------------------
__global__ void __launch_bounds__(256) cvtw_kernel(
    const float* __restrict__ w1, const float* __restrict__ w2)
{
    int i = blockIdx.x * 256 + threadIdx.x;
    if (i < NH1 * NKE) g_w1[i] = f2tf_f(w1[i]);
    if (i < NE * NH1)  g_w2[i] = f2tf_f(w2[i]);
}

// ---------------------------------------------------------------------------
// Kernel 1: top-K nearest unvisited + gather + pad-avg -> g_emb (tf32-rounded)
// One warp per (b, r) row. 4 warps / block.
// Selection: cached per-lane argmin + redux.sync reductions per round.
// ---------------------------------------------------------------------------
__global__ void __launch_bounds__(128) prep_kernel(
    const int*   __restrict__ current,
    const float* __restrict__ distance,
    const float* __restrict__ masked,
    const float* __restrict__ enc)
{
    const int row  = blockIdx.x * 4 + (threadIdx.x >> 5);
    const int lane = threadIdx.x & 31;
    const int b    = row / NR;
    const uint32_t INFB = 0x7f800000u;
    const float FINF = __uint_as_float(INFB);

    const float* mrow = masked + (size_t)row * NN;
    const float* drow = distance + ((size_t)b * NN + current[row]) * NN;

    // Each lane owns candidates n = lane + 32*j, j in [0,16)
    float v[16];
#pragma unroll
    for (int j = 0; j < 16; j++) {
        int n = lane + 32 * j;
        float val = FINF;
        if (n < NN) {
            float m = __ldg(mrow + n);        // 0.0 (unvisited) or -inf (visited)
            if (m > -1e37f) val = __ldg(drow + n);
        }
        v[j] = val;
    }

    // Per-lane cached argmin (strict < keeps lowest index on ties)
    float lv = v[0]; int lj = 0;
#pragma unroll
    for (int j = 1; j < 16; j++)
        if (v[j] < lv) { lv = v[j]; lj = j; }

    int sel[NK];
#pragma unroll
    for (int k = 0; k < NK; k++) {
        uint32_t lvb = __float_as_uint(lv);   // dist >= 0 -> bit order == value order
        uint32_t gvb = __reduce_min_sync(0xffffffffu, lvb);
        uint32_t myn = (lvb == gvb) ? (uint32_t)(lane + 32 * lj) : 0xffffffffu;
        uint32_t gn  = __reduce_min_sync(0xffffffffu, myn);
        if (gvb < INFB) {
            sel[k] = (int)gn;
            if (myn == gn) {  // unique winner lane: clear slot, rescan locally
#pragma unroll
                for (int j = 0; j < 16; j++)
                    if (j == lj) v[j] = FINF;
                lv = v[0]; lj = 0;
#pragma unroll
                for (int j = 1; j < 16; j++)
                    if (v[j] < lv) { lv = v[j]; lj = j; }
            }
        } else {
            sel[k] = NN;  // padding index
        }
    }

    // Gather + pad-avg. Each lane handles 4 contiguous channels (float4).
    float4 acc = make_float4(0.f, 0.f, 0.f, 0.f);
    int cnt = 0;
#pragma unroll
    for (int k = 0; k < NK; k++) {
        if (sel[k] < NN) {
            cnt++;
            float4 e = *(const float4*)(enc + ((size_t)b * NN + sel[k]) * NE + lane * 4);
            acc.x += e.x; acc.y += e.y; acc.z += e.z; acc.w += e.w;
        }
    }
    float cf = (cnt > 0) ? (float)cnt : 1.0f;   // cnt==0 -> acc==0 -> mean 0
    float4 mean = make_float4(f2tf_f(acc.x / cf), f2tf_f(acc.y / cf),
                              f2tf_f(acc.z / cf), f2tf_f(acc.w / cf));

    float* erow = g_emb + (size_t)row * NKE + lane * 4;
#pragma unroll
    for (int k = 0; k < NK; k++) {
        float4 o;
        if (sel[k] < NN) {
            float4 e = *(const float4*)(enc + ((size_t)b * NN + sel[k]) * NE + lane * 4);
            o = make_float4(f2tf_f(e.x), f2tf_f(e.y), f2tf_f(e.z), f2tf_f(e.w));
        } else {
            o = mean;
        }
        *(float4*)(erow + k * NE) = o;
    }
}

// ---------------------------------------------------------------------------
// tf32 mma.sync GEMM, cp.async 3-stage pipeline.
// C[M,Nn] = A[M,Kk] * W[Nn,Kk]^T (+bias, optional ReLU(+tf32 round))
// Block tile 128x128, BK=32, 8 warps (2x4), warp tile 64x32.
// WHICH==1: g_emb -> g_h (g_w1, b1, ReLU, round).  WHICH==2: g_h -> out.
// ---------------------------------------------------------------------------
#define BM   128
#define BN   128
#define BK   32
#define SSTG 3
#define AW   (BK + 4)          // 36 words/row (16B-aligned row stride, padded)
#define TILEW (BM * AW)        // words per operand stage (both operands 128 rows)
#define SMEMSZ (SSTG * 2 * TILEW * 4)   // 110592 bytes

__device__ __forceinline__ void cp16(uint32_t s, const void* g) {
    asm volatile("cp.async.cg.shared.global [%0], [%1], 16;\n" :: "r"(s), "l"(g));
}
__device__ __forceinline__ void cpcommit() {
    asm volatile("cp.async.commit_group;\n" ::);
}
template<int Npend> __device__ __forceinline__ void cpwait() {
    asm volatile("cp.async.wait_group %0;\n" :: "n"(Npend));
}

template<int WHICH>
__global__ void __launch_bounds__(256, 2) gemm_kernel(
    const float* __restrict__ bias, float* __restrict__ Cout)
{
    constexpr int  Kk   = (WHICH == 1) ? NKE : NH1;
    constexpr int  Nn   = (WHICH == 1) ? NH1 : NE;
    constexpr bool RELU = (WHICH == 1);
    const float* A = (WHICH == 1) ? g_emb : g_h;
    const float* W = (WHICH == 1) ? g_w1  : g_w2;
    float*       C = (WHICH == 1) ? g_h   : Cout;

    extern __shared__ float smem[];
    const uint32_t sbase = (uint32_t)__cvta_generic_to_shared(smem);

    const int m0   = blockIdx.y * BM;
    const int n0   = blockIdx.x * BN;
    const int t    = threadIdx.x;
    const int lane = t & 31;
    const int w    = t >> 5;
    const int wm   = w >> 2;   // 0..1 (M)
    const int wn   = w & 3;    // 0..3 (N)
    const int tr   = t >> 3;       // 0..31
    const int tc   = (t & 7) * 4;  // 0,4,..28

    float acc[4][4][4];
#pragma unroll
    for (int i = 0; i < 4; i++)
#pragma unroll
        for (int j = 0; j < 4; j++)
#pragma unroll
            for (int q = 0; q < 4; q++) acc[i][j][q] = 0.f;

    constexpr int NT = Kk / BK;

    auto issue = [&](int it) {
        const int k0 = it * BK;
        uint32_t sa = sbase + (uint32_t)(it % SSTG) * (2 * TILEW * 4);
        uint32_t sb = sa + TILEW * 4;
        const float* ga = A + (size_t)(m0 + tr) * Kk + k0 + tc;
        const float* gw = W + (size_t)(n0 + tr) * Kk + k0 + tc;
        uint32_t da = sa + (uint32_t)(tr * AW + tc) * 4;
        uint32_t db = sb + (uint32_t)(tr * AW + tc) * 4;
#pragma unroll
        for (int p = 0; p < 4; p++) {
            cp16(da + p * 32 * AW * 4, ga + (size_t)p * 32 * Kk);
            cp16(db + p * 32 * AW * 4, gw + (size_t)p * 32 * Kk);
        }
    };

    // Prologue: stages 0, 1 in flight
    issue(0); cpcommit();
    issue(1); cpcommit();

    for (int it = 0; it < NT; it++) {
        cpwait<SSTG - 2>();
        __syncthreads();            // stage `it` visible to all; prior compute done
        if (it + SSTG - 1 < NT) issue(it + SSTG - 1);
        cpcommit();                 // keep group count aligned

        const uint32_t* As = (const uint32_t*)(smem + (it % SSTG) * 2 * TILEW);
        const uint32_t* Bs = As + TILEW;

#pragma unroll
        for (int kk = 0; kk < BK; kk += 8) {
            const int kc = kk + (lane & 3);
            uint32_t a[4][4];
#pragma unroll
            for (int mt = 0; mt < 4; mt++) {
                const int mr = wm * 64 + mt * 16 + (lane >> 2);
                a[mt][0] = As[mr * AW + kc];
                a[mt][1] = As[(mr + 8) * AW + kc];
                a[mt][2] = As[mr * AW + kc + 4];
                a[mt][3] = As[(mr + 8) * AW + kc + 4];
            }
            uint32_t bb[4][2];
#pragma unroll
            for (int nt = 0; nt < 4; nt++) {
                const int nc = wn * 32 + nt * 8 + (lane >> 2);
                bb[nt][0] = Bs[nc * AW + kc];
                bb[nt][1] = Bs[nc * AW + kc + 4];
            }
#pragma unroll
            for (int mt = 0; mt < 4; mt++)
#pragma unroll
                for (int nt = 0; nt < 4; nt++) {
                    asm volatile(
                        "mma.sync.aligned.m16n8k8.row.col.f32.tf32.tf32.f32 "
                        "{%0,%1,%2,%3}, {%4,%5,%6,%7}, {%8,%9}, {%0,%1,%2,%3};\n"
                        : "+f"(acc[mt][nt][0]), "+f"(acc[mt][nt][1]),
                          "+f"(acc[mt][nt][2]), "+f"(acc[mt][nt][3])
                        : "r"(a[mt][0]), "r"(a[mt][1]), "r"(a[mt][2]), "r"(a[mt][3]),
                          "r"(bb[nt][0]), "r"(bb[nt][1]));
                }
        }
        __syncthreads();            // all done reading stage before it is reused
    }

    // Epilogue: bias (+ReLU + tf32 round for WHICH==1), float2 stores
#pragma unroll
    for (int mt = 0; mt < 4; mt++) {
#pragma unroll
        for (int nt = 0; nt < 4; nt++) {
            const int mr = m0 + wm * 64 + mt * 16 + (lane >> 2);
            const int nc = n0 + wn * 32 + nt * 8 + (lane & 3) * 2;
            float bx = __ldg(bias + nc);
            float by = __ldg(bias + nc + 1);
            float2 r0 = make_float2(acc[mt][nt][0] + bx, acc[mt][nt][1] + by);
            float2 r1 = make_float2(acc[mt][nt][2] + bx, acc[mt][nt][3] + by);
            if (RELU) {
                r0.x = f2tf_f(fmaxf(r0.x, 0.f)); r0.y = f2tf_f(fmaxf(r0.y, 0.f));
                r1.x = f2tf_f(fmaxf(r1.x, 0.f)); r1.y = f2tf_f(fmaxf(r1.y, 0.f));
            }
            *(float2*)(C + (size_t)mr * Nn + nc)       = r0;
            *(float2*)(C + (size_t)(mr + 8) * Nn + nc) = r1;
        }
    }
}

// ---------------------------------------------------------------------------
extern "C" void kernel_launch(void* const* d_in, const int* in_sizes, int n_in,
                              void* d_out, int out_size)
{
    const int*   current  = (const int*)  d_in[0];
    const float* distance = (const float*)d_in[1];
    const float* masked   = (const float*)d_in[2];
    const float* enc      = (const float*)d_in[3];
    const float* w1       = (const float*)d_in[4];
    const float* b1       = (const float*)d_in[5];
    const float* w2       = (const float*)d_in[6];
    const float* b2       = (const float*)d_in[7];
    float* out = (float*)d_out;

    cudaFuncSetAttribute(gemm_kernel<1>,
                         cudaFuncAttributeMaxDynamicSharedMemorySize, SMEMSZ);
    cudaFuncSetAttribute(gemm_kernel<2>,
                         cudaFuncAttributeMaxDynamicSharedMemorySize, SMEMSZ);

    cvtw_kernel<<<(NH1 * NKE + 255) / 256, 256>>>(w1, w2);
    prep_kernel<<<NM / 4, 128>>>(current, distance, masked, enc);
    gemm_kernel<1><<<dim3(NH1 / BN, NM / BM), 256, SMEMSZ>>>(b1, nullptr);
    gemm_kernel<2><<<dim3(NE  / BN, NM / BM), 256, SMEMSZ>>>(b2, out);
}